// round 1
// baseline (speedup 1.0000x reference)
#include <cuda_runtime.h>
#include <cstdint>

// Problem constants (fixed by the reference)
#define B_DIM 16
#define S_DIM 4096
#define H_DIM 768
#define NUM_WORDS 2048          // S/2
#define VEC (H_DIM / 4)         // 192 float4 per row

// One block per (word, batch) output row.
// word_ids[b, 1..S-2] is non-decreasing (cumsum construction); positions 0 and
// S-1 are -1 (CLS/SEP, dropped). Binary search gives the contiguous token run
// for word w; average its rows. Traffic-optimal: every input row read once,
// every output row written once.
__global__ __launch_bounds__(VEC) void seg_mean_kernel(
    const float* __restrict__ hs,   // [B, S, H]
    const int*   __restrict__ wid,  // [B, S]
    float*       __restrict__ out)  // [B, NUM_WORDS, H]
{
    const int w = blockIdx.x;       // word index
    const int b = blockIdx.y;       // batch index

    const int* __restrict__ row = wid + (size_t)b * S_DIM;

    // lower_bound of w in row[1 .. S-2] (search range [1, S-1))
    int lo = 1, hi = S_DIM - 1;
    while (lo < hi) {
        int mid = (lo + hi) >> 1;
        if (row[mid] < w) lo = mid + 1; else hi = mid;
    }
    const int start = lo;

    // upper_bound of w
    hi = S_DIM - 1;
    while (lo < hi) {
        int mid = (lo + hi) >> 1;
        if (row[mid] <= w) lo = mid + 1; else hi = mid;
    }
    const int end = lo;

    const int cnt = end - start;
    const float inv = (cnt > 0) ? (1.0f / (float)cnt) : 0.0f;

    const float4* __restrict__ base =
        (const float4*)(hs + (size_t)b * S_DIM * H_DIM);
    const int c = threadIdx.x;      // 0..191, one float4 column per thread

    float4 acc = make_float4(0.f, 0.f, 0.f, 0.f);
    for (int t = start; t < end; ++t) {
        float4 v = base[(size_t)t * VEC + c];
        acc.x += v.x; acc.y += v.y; acc.z += v.z; acc.w += v.w;
    }

    acc.x *= inv; acc.y *= inv; acc.z *= inv; acc.w *= inv;

    float4* __restrict__ ob =
        (float4*)(out + ((size_t)b * NUM_WORDS + w) * H_DIM);
    ob[c] = acc;
}

extern "C" void kernel_launch(void* const* d_in, const int* in_sizes, int n_in,
                              void* d_out, int out_size)
{
    const float* hs  = (const float*)d_in[0];   // hidden_states [B,S,H] f32
    const int*   wid = (const int*)d_in[1];     // word_ids [B,S] i32
    float*       out = (float*)d_out;           // [B, NUM_WORDS, H] f32

    dim3 grid(NUM_WORDS, B_DIM);
    seg_mean_kernel<<<grid, VEC>>>(hs, wid, out);
}

// round 2
// speedup vs baseline: 1.6818x; 1.6818x over previous
#include <cuda_runtime.h>
#include <cstdint>

// Problem constants (fixed by the reference)
#define B_DIM 16
#define S_DIM 4096
#define H_DIM 768
#define NUM_WORDS 2048          // S/2
#define VEC (H_DIM / 4)         // 192 float4 per row
#define WPB 8                   // words per block in main kernel

// Scratch: word start-token table, [B][NUM_WORDS+1].
// starts[b][w] = first token t with wid[b][t]==w; default S-1 (=> empty word).
// end(w) = starts[b][w+1] works because words are contiguous 0..max and the
// last valid token is S-2 (token S-1 is SEP = -1).
__device__ int g_starts[B_DIM * (NUM_WORDS + 1)];

__global__ void init_starts_kernel() {
    int i = blockIdx.x * blockDim.x + threadIdx.x;
    if (i < B_DIM * (NUM_WORDS + 1)) g_starts[i] = S_DIM - 1;
}

// One thread per token: mark segment starts.
__global__ void scatter_starts_kernel(const int* __restrict__ wid) {
    const int b = blockIdx.y;
    const int t = blockIdx.x * blockDim.x + threadIdx.x;
    if (t < 1 || t >= S_DIM) return;
    const int* row = wid + (size_t)b * S_DIM;
    int w = row[t];
    if (w >= 0 && row[t - 1] != w) {
        g_starts[b * (NUM_WORDS + 1) + w] = t;
    }
}

// One block per (8 words, batch). Thread c owns float4 column c of the row.
// The 8 words' token runs are contiguous -> block streams one contiguous
// input chunk and writes 8 contiguous output rows.
__global__ __launch_bounds__(VEC) void seg_mean_kernel(
    const float4* __restrict__ hs,   // [B, S, VEC]
    float4*       __restrict__ out)  // [B, NUM_WORDS, VEC]
{
    const int b  = blockIdx.y;
    const int w0 = blockIdx.x * WPB;
    const int c  = threadIdx.x;

    __shared__ int sb[WPB + 1];
    if (c <= WPB) sb[c] = g_starts[b * (NUM_WORDS + 1) + w0 + c];
    __syncthreads();

    const float4* __restrict__ base = hs + (size_t)b * S_DIM * VEC;
    float4* __restrict__ ob = out + ((size_t)b * NUM_WORDS + w0) * VEC;

#pragma unroll
    for (int i = 0; i < WPB; ++i) {
        const int s = sb[i];
        const int e = sb[i + 1];
        float4 acc = make_float4(0.f, 0.f, 0.f, 0.f);
        for (int t = s; t < e; ++t) {
            float4 v = base[(size_t)t * VEC + c];
            acc.x += v.x; acc.y += v.y; acc.z += v.z; acc.w += v.w;
        }
        const float inv = (e > s) ? (1.0f / (float)(e - s)) : 0.0f;
        acc.x *= inv; acc.y *= inv; acc.z *= inv; acc.w *= inv;
        ob[(size_t)i * VEC + c] = acc;
    }
}

extern "C" void kernel_launch(void* const* d_in, const int* in_sizes, int n_in,
                              void* d_out, int out_size)
{
    const float* hs  = (const float*)d_in[0];   // hidden_states [B,S,H] f32
    const int*   wid = (const int*)d_in[1];     // word_ids [B,S] i32
    float*       out = (float*)d_out;           // [B, NUM_WORDS, H] f32

    {
        int n = B_DIM * (NUM_WORDS + 1);
        init_starts_kernel<<<(n + 255) / 256, 256>>>();
    }
    {
        dim3 grid(S_DIM / 256, B_DIM);
        scatter_starts_kernel<<<grid, 256>>>(wid);
    }
    {
        dim3 grid(NUM_WORDS / WPB, B_DIM);
        seg_mean_kernel<<<grid, VEC>>>((const float4*)hs, (float4*)out);
    }
}